// round 1
// baseline (speedup 1.0000x reference)
#include <cuda_runtime.h>

// ApsUp: polyphase 2x upsample + circular-pad + depthwise 3x3 binomial blur,
// collapsed to a direct gather (only one phase per batch is nonzero).
//
// Shapes (fixed): inp [16,256,64,64] f32, poly [16] i32, out [16,256,128,128] f32.
//
// Phase p = r + 2c (r = row offset, c = col offset). Separable weights [1,2,1]/4.
// Output row i: i==r (mod2) -> 0.5 * row A=(i-r)/2 ; else 0.25*(row A) + 0.25*(row A +/- 1).
// Same for columns with offset c. All wraps are circular (mod 64).

#define B_ 16
#define C_ 256
#define N_ 64
#define TWO_N 128

__global__ __launch_bounds__(256) void aps_up_kernel(
    const float* __restrict__ inp,
    const int*   __restrict__ poly,
    float*       __restrict__ out)
{
    int idx = blockIdx.x * blockDim.x + threadIdx.x;
    // Decompose: T (fastest, 32 col-tiles of 4 output cols), A (64 row pairs),
    // ch (256), bb (16). Total threads = 16*256*64*32 = 2^23.
    int T  = idx & 31;
    int A  = (idx >> 5) & 63;
    int ch = (idx >> 11) & 255;
    int bb = idx >> 19;

    int p = __ldg(&poly[bb]);
    int r = p & 1;
    int c = p >> 1;

    // Input rows needed: a0 = A, a1 = A - 1 (if r==1) or A + 1 (if r==0), circular.
    int a0 = A;
    int a1 = (A + (r ? (N_ - 1) : 1)) & (N_ - 1);

    // Input cols needed: 3 consecutive starting at 2T - c, circular.
    int cs = 2 * T - c;
    int j0 = (cs     + N_) & (N_ - 1);
    int j1 = (cs + 1 + N_) & (N_ - 1);
    int j2 = (cs + 2 + N_) & (N_ - 1);

    const float* base = inp + ((size_t)(bb * C_ + ch)) * (N_ * N_);
    const float* row0 = base + a0 * N_;
    const float* row1 = base + a1 * N_;

    float xa0 = row0[j0], xa1 = row0[j1], xa2 = row0[j2];
    float xb0 = row1[j0], xb1 = row1[j1], xb2 = row1[j2];

    float* obase = out
        + ((size_t)(bb * C_ + ch)) * (TWO_N * TWO_N)
        + (size_t)(2 * A) * TWO_N
        + 4 * T;

#pragma unroll
    for (int s = 0; s < 2; ++s) {
        // Row combine: output row 2A+s.
        float R0 = (s == r) ? 0.5f  : 0.25f;  // weight on row a0 (=A)
        float R1 = (s == r) ? 0.0f  : 0.25f;  // weight on row a1
        float y0 = R0 * xa0 + R1 * xb0;
        float y1 = R0 * xa1 + R1 * xb1;
        float y2 = R0 * xa2 + R1 * xb2;

        // Column combine for output cols 4T .. 4T+3.
        float4 o;
        if (c == 0) {
            // loaded cols: y0=B0, y1=B0+1, y2=B0+2  (B0 = 2T)
            o.x = 0.5f  * y0;
            o.y = 0.25f * (y0 + y1);
            o.z = 0.5f  * y1;
            o.w = 0.25f * (y1 + y2);
        } else {
            // loaded cols: y0=B0-1, y1=B0, y2=B0+1
            o.x = 0.25f * (y0 + y1);
            o.y = 0.5f  * y1;
            o.z = 0.25f * (y1 + y2);
            o.w = 0.5f  * y2;
        }
        *reinterpret_cast<float4*>(obase + s * TWO_N) = o;
    }
}

extern "C" void kernel_launch(void* const* d_in, const int* in_sizes, int n_in,
                              void* d_out, int out_size)
{
    const float* inp  = (const float*)d_in[0];
    const int*   poly = (const int*)d_in[1];
    float*       out  = (float*)d_out;

    // 16*256*64*32 threads = 8388608 -> 32768 blocks of 256
    const int total  = B_ * C_ * N_ * (N_ / 2);
    const int tpb    = 256;
    const int blocks = total / tpb;
    aps_up_kernel<<<blocks, tpb>>>(inp, poly, out);
}